// round 1
// baseline (speedup 1.0000x reference)
#include <cuda_runtime.h>
#include <cuda_bf16.h>

// Problem constants
#define BDIM   16
#define IMG_H  512
#define IMG_W  512
#define FH     32
#define FW     32
#define NBOX   16
#define CCH    256     // conv out channels
#define DDIM   256     // dense out
#define KDIM   768     // 16*16*3
#define M_TOT  16384   // B*32*32
#define S_ROI  7

// Scratch (static __device__ — no allocations allowed)
__device__ float g_A[M_TOT * KDIM];       // im2col patches  [16384, 768]  ~50 MB
__device__ float g_feat[M_TOT * CCH];     // conv+relu feat  [16384, 256]  ~17 MB
__device__ float g_obj[BDIM * NBOX * CCH]; // pooled rois    [256, 256]

// ---------------------------------------------------------------------------
// 1) im2col: patches are disjoint (stride == kernel), pure gather/reshape.
//    One float4 per thread; k%48 runs are contiguous in the image, 4 | 48,
//    so every aligned float4 in k maps to a contiguous, aligned image float4.
// ---------------------------------------------------------------------------
__global__ __launch_bounds__(256) void im2col_kernel(const float* __restrict__ img) {
    int id = blockIdx.x * blockDim.x + threadIdx.x;     // one float4
    int fidx = id * 4;
    int m = fidx / KDIM;
    int k = fidx - m * KDIM;
    int b  = m >> 10;
    int oy = (m >> 5) & 31;
    int ox = m & 31;
    int ky  = k / 48;
    int rem = k - ky * 48;  // kx*3 + c (contiguous in image)
    const float* src = img + ((size_t)((b * 512 + oy * 16 + ky) * 512 + ox * 16) * 3 + rem);
    *(float4*)&g_A[fidx] = *(const float4*)src;
}

// ---------------------------------------------------------------------------
// 2) Conv-as-GEMM: C[16384,256] = A[16384,768] @ W[768,256], + bias, ReLU.
//    Classic SMEM-tiled fp32 SGEMM: BM=128, BN=128, BK=16, 8x8 per thread.
// ---------------------------------------------------------------------------
#define BM 128
#define BN 128
#define BK 16

__global__ __launch_bounds__(256) void conv_gemm_kernel(
    const float* __restrict__ W,      // [768, 256] (HWIO flattened)
    const float* __restrict__ bias)   // [256]
{
    __shared__ float As[BK][BM];
    __shared__ float Bs[BK][BN];

    const int bn = blockIdx.x;        // 0..1
    const int bm = blockIdx.y;        // 0..127
    const int tid = threadIdx.x;
    const int tx = tid & 15;          // n-dir
    const int ty = tid >> 4;          // m-dir
    const int m0 = bm * BM;
    const int n0 = bn * BN;

    float acc[8][8];
    #pragma unroll
    for (int i = 0; i < 8; i++)
        #pragma unroll
        for (int j = 0; j < 8; j++) acc[i][j] = 0.f;

    for (int k0 = 0; k0 < KDIM; k0 += BK) {
        // Load A tile 128x16 (transposed into As[k][m])
        #pragma unroll
        for (int it = 0; it < 2; it++) {
            int t = tid + it * 256;           // 0..511
            int row = t >> 2;                 // 0..127
            int c4 = (t & 3) * 4;             // 0,4,8,12
            float4 v = *(const float4*)&g_A[(m0 + row) * KDIM + k0 + c4];
            As[c4 + 0][row] = v.x;
            As[c4 + 1][row] = v.y;
            As[c4 + 2][row] = v.z;
            As[c4 + 3][row] = v.w;
        }
        // Load B tile 16x128
        #pragma unroll
        for (int it = 0; it < 2; it++) {
            int t = tid + it * 256;
            int row = t >> 5;                 // 0..15
            int c4 = (t & 31) * 4;            // 0..124
            *(float4*)&Bs[row][c4] = *(const float4*)&W[(k0 + row) * CCH + n0 + c4];
        }
        __syncthreads();

        #pragma unroll
        for (int kk = 0; kk < BK; kk++) {
            float a[8], bfr[8];
            #pragma unroll
            for (int i = 0; i < 8; i++) a[i] = As[kk][ty * 8 + i];
            #pragma unroll
            for (int j = 0; j < 8; j++) bfr[j] = Bs[kk][tx * 8 + j];
            #pragma unroll
            for (int i = 0; i < 8; i++)
                #pragma unroll
                for (int j = 0; j < 8; j++)
                    acc[i][j] += a[i] * bfr[j];
        }
        __syncthreads();
    }

    // Epilogue: bias + relu
    #pragma unroll
    for (int i = 0; i < 8; i++) {
        int m = m0 + ty * 8 + i;
        #pragma unroll
        for (int j = 0; j < 8; j++) {
            int n = n0 + tx * 8 + j;
            float v = acc[i][j] + bias[n];
            g_feat[m * CCH + n] = v > 0.f ? v : 0.f;
        }
    }
}

// ---------------------------------------------------------------------------
// 3) ROI align (bilinear, 7x7 samples) + mean + notrack mask.
//    One block per roi; one thread per channel (coalesced feature reads).
// ---------------------------------------------------------------------------
__global__ __launch_bounds__(256) void roi_kernel(
    const float* __restrict__ boxes)  // [B*N, 4]
{
    const int roi = blockIdx.x;       // 0..255
    const int b = roi >> 4;
    const int c = threadIdx.x;

    float4 box = *(const float4*)&boxes[roi * 4];
    float ymin = box.x, xmin = box.y, ymax = box.z, xmax = box.w;

    bool empty = (ymin == -1.f) && (xmin == -1.f) && (ymax == -1.f) && (xmax == -1.f);
    if (empty) { g_obj[roi * CCH + c] = 0.f; return; }

    int y0[S_ROI], y1[S_ROI], x0[S_ROI], x1[S_ROI];
    float wy[S_ROI], wx[S_ROI];
    #pragma unroll
    for (int i = 0; i < S_ROI; i++) {
        float step = ((float)i + 0.5f) / (float)S_ROI;
        float ys = ymin + (ymax - ymin) * step;
        float xs = xmin + (xmax - xmin) * step;
        float py = ys * (float)FH - 0.5f;
        float px = xs * (float)FW - 0.5f;
        float y0f = floorf(py), x0f = floorf(px);
        wy[i] = py - y0f;
        wx[i] = px - x0f;
        int yi = (int)y0f, xi = (int)x0f;
        y0[i] = min(max(yi, 0), FH - 1);
        y1[i] = min(max(yi + 1, 0), FH - 1);
        x0[i] = min(max(xi, 0), FW - 1);
        x1[i] = min(max(xi + 1, 0), FW - 1);
    }

    const float* fb = g_feat + (size_t)b * FH * FW * CCH;
    float acc = 0.f;
    #pragma unroll
    for (int i = 0; i < S_ROI; i++) {
        const float* ry0 = fb + y0[i] * (FW * CCH);
        const float* ry1 = fb + y1[i] * (FW * CCH);
        float wyi = wy[i];
        #pragma unroll
        for (int j = 0; j < S_ROI; j++) {
            float wxj = wx[j];
            float f00 = ry0[x0[j] * CCH + c];
            float f01 = ry0[x1[j] * CCH + c];
            float f10 = ry1[x0[j] * CCH + c];
            float f11 = ry1[x1[j] * CCH + c];
            acc += (1.f - wyi) * (1.f - wxj) * f00
                 + (1.f - wyi) * wxj         * f01
                 + wyi         * (1.f - wxj) * f10
                 + wyi         * wxj         * f11;
        }
    }
    g_obj[roi * CCH + c] = acc * (1.f / (S_ROI * S_ROI));
}

// ---------------------------------------------------------------------------
// 4) Dense: out[256,256] = obj[256,256] @ Wd[256,256] + bd.
//    16 rows per block; W column per thread (coalesced).
// ---------------------------------------------------------------------------
__global__ __launch_bounds__(256) void dense_kernel(
    const float* __restrict__ Wd,     // [256, 256]
    const float* __restrict__ bd,     // [256]
    float* __restrict__ out)          // [256, 256]
{
    __shared__ float sObj[16][DDIM];
    const int r0 = blockIdx.x * 16;
    const int tid = threadIdx.x;

    #pragma unroll
    for (int r = 0; r < 16; r++)
        sObj[r][tid] = g_obj[(r0 + r) * CCH + tid];
    __syncthreads();

    float acc[16];
    #pragma unroll
    for (int r = 0; r < 16; r++) acc[r] = 0.f;

    for (int k = 0; k < CCH; k++) {
        float w = Wd[k * DDIM + tid];
        #pragma unroll
        for (int r = 0; r < 16; r++)
            acc[r] += sObj[r][k] * w;
    }

    float bb = bd[tid];
    #pragma unroll
    for (int r = 0; r < 16; r++)
        out[(r0 + r) * DDIM + tid] = acc[r] + bb;
}

// ---------------------------------------------------------------------------
// Launch
// Inputs: 0 images[16,512,512,3] f32, 1 bboxes[16,16,4] f32,
//         2 conv_w[16,16,3,256] f32, 3 conv_b[256] f32,
//         4 dense_w[256,256] f32, 5 dense_b[256] f32
// Output: [16,16,256] f32
// ---------------------------------------------------------------------------
extern "C" void kernel_launch(void* const* d_in, const int* in_sizes, int n_in,
                              void* d_out, int out_size) {
    const float* images  = (const float*)d_in[0];
    const float* bboxes  = (const float*)d_in[1];
    const float* conv_w  = (const float*)d_in[2];
    const float* conv_b  = (const float*)d_in[3];
    const float* dense_w = (const float*)d_in[4];
    const float* dense_b = (const float*)d_in[5];
    float* out = (float*)d_out;

    // 1) im2col: 16384*768 floats = 3145728 float4s
    im2col_kernel<<<(M_TOT * KDIM / 4) / 256, 256>>>(images);

    // 2) conv GEMM + bias + relu
    dim3 gemm_grid(CCH / BN, M_TOT / BM);   // (2, 128)
    conv_gemm_kernel<<<gemm_grid, 256>>>(conv_w, conv_b);

    // 3) roi align + mean + mask
    roi_kernel<<<BDIM * NBOX, CCH>>>(bboxes);

    // 4) dense
    dense_kernel<<<(BDIM * NBOX) / 16, DDIM>>>(dense_w, dense_b, out);
}

// round 3
// speedup vs baseline: 2.6802x; 2.6802x over previous
#include <cuda_runtime.h>
#include <cuda_bf16.h>
#include <cstdint>

// ---------------------------------------------------------------------------
// Problem constants
// ---------------------------------------------------------------------------
#define BDIM   16
#define FH     32
#define FW     32
#define NBOX   16
#define CCH    256     // conv out channels
#define DDIM   256     // dense out
#define KDIM   768     // 16*16*3
#define M_TOT  16384   // B*32*32
#define S_ROI  7

// Scratch (static __device__ — no allocations allowed)
__device__ float g_feat[M_TOT * CCH];       // conv+relu feat [16384, 256]
__device__ float g_obj[BDIM * NBOX * CCH];  // pooled rois   [256, 256]

// ---------------------------------------------------------------------------
// tf32 mma.sync helpers (sm_80+ path; compiles for plain sm_100 target)
// ---------------------------------------------------------------------------
__device__ __forceinline__ uint32_t f2tf32(float f) {
    uint32_t r;
    asm("cvt.rna.tf32.f32 %0, %1;" : "=r"(r) : "f"(f));
    return r;
}

__device__ __forceinline__ void mma_tf32(float* d, const uint32_t* a, const uint32_t* b) {
    asm volatile(
        "mma.sync.aligned.m16n8k8.row.col.f32.tf32.tf32.f32 "
        "{%0,%1,%2,%3}, {%4,%5,%6,%7}, {%8,%9}, {%0,%1,%2,%3};"
        : "+f"(d[0]), "+f"(d[1]), "+f"(d[2]), "+f"(d[3])
        : "r"(a[0]), "r"(a[1]), "r"(a[2]), "r"(a[3]), "r"(b[0]), "r"(b[1]));
}

// ---------------------------------------------------------------------------
// 1) Conv-as-GEMM with fused im2col.
//    C[16384,256] = A[16384,768] @ W[768,256], + bias, ReLU.
//    CTA tile 128(M) x 128(N), BK=32, double-buffered SMEM.
//    8 warps, each 64(M) x 32(N) -> mma grid 4x4 of m16n8k8.
// ---------------------------------------------------------------------------
#define BK   32
#define NCH  (KDIM / BK)      // 24 k-chunks
#define LDA  36               // padded (conflict-free A frag LDS: bank = 4m+k)
#define LDB  132              // padded
#define A_WORDS (128 * LDA)   // per stage
#define B_WORDS (BK * LDB)
#define SMEM_BYTES ((2 * A_WORDS + 2 * B_WORDS) * 4)   // 70656

__global__ __launch_bounds__(256, 1) void conv_mma_kernel(
    const float* __restrict__ img,     // [16,512,512,3]
    const float* __restrict__ W,       // [768,256] (HWIO flat) — already [k][n]
    const float* __restrict__ bias)    // [256]
{
    extern __shared__ float smem[];
    float* As = smem;                  // [2][128][LDA]
    float* Bs = smem + 2 * A_WORDS;    // [2][BK][LDB]

    const int tid = threadIdx.x;
    const int wid = tid >> 5;
    const int lid = tid & 31;
    const int g   = lid >> 2;          // group id 0..7
    const int t4  = lid & 3;           // thread-in-group 0..3
    const int wm  = wid & 1;           // 2 warps in M (64 each)
    const int wn  = wid >> 1;          // 4 warps in N (32 each)

    const int n0 = blockIdx.x * 128;   // 0 or 128
    const int m0 = blockIdx.y * 128;

    float acc[4][4][4];
    #pragma unroll
    for (int i = 0; i < 4; i++)
        #pragma unroll
        for (int j = 0; j < 4; j++)
            #pragma unroll
            for (int r = 0; r < 4; r++) acc[i][j][r] = 0.f;

    float4 aReg[4], bReg[4];

    // --- tile loaders: global -> registers (im2col fused for A) ---
    auto loadA = [&](int c) {
        const int k0 = c * BK;
        #pragma unroll
        for (int i = 0; i < 4; i++) {
            int f4  = tid + i * 256;        // 0..1023
            int row = f4 >> 3;              // 0..127
            int c4  = (f4 & 7) * 4;         // 0..28
            int m   = m0 + row;
            int b   = m >> 10;
            int oy  = (m >> 5) & 31;
            int ox  = m & 31;
            int k   = k0 + c4;
            int ky  = k / 48;
            int rem = k - ky * 48;          // within 48-float pixel run; 4|48 so no crossing
            aReg[i] = *(const float4*)(
                img + (size_t)((b * 512 + oy * 16 + ky) * 512 + ox * 16) * 3 + rem);
        }
    };
    auto loadB = [&](int c) {
        const int k0 = c * BK;
        #pragma unroll
        for (int i = 0; i < 4; i++) {
            int f4  = tid + i * 256;        // 0..1023
            int row = f4 >> 5;              // 0..31
            int c4  = (f4 & 31) * 4;        // 0..124
            bReg[i] = *(const float4*)&W[(k0 + row) * CCH + n0 + c4];
        }
    };
    // --- registers -> SMEM with tf32 rounding ---
    auto stsA = [&](int s) {
        float* dst = As + s * A_WORDS;
        #pragma unroll
        for (int i = 0; i < 4; i++) {
            int f4  = tid + i * 256;
            int row = f4 >> 3;
            int c4  = (f4 & 7) * 4;
            uint4 v;
            v.x = f2tf32(aReg[i].x); v.y = f2tf32(aReg[i].y);
            v.z = f2tf32(aReg[i].z); v.w = f2tf32(aReg[i].w);
            *(uint4*)&dst[row * LDA + c4] = v;
        }
    };
    auto stsB = [&](int s) {
        float* dst = Bs + s * B_WORDS;
        #pragma unroll
        for (int i = 0; i < 4; i++) {
            int f4  = tid + i * 256;
            int row = f4 >> 5;
            int c4  = (f4 & 31) * 4;
            uint4 v;
            v.x = f2tf32(bReg[i].x); v.y = f2tf32(bReg[i].y);
            v.z = f2tf32(bReg[i].z); v.w = f2tf32(bReg[i].w);
            *(uint4*)&dst[row * LDB + c4] = v;
        }
    };

    // --- prologue ---
    loadA(0); loadB(0);
    stsA(0);  stsB(0);
    __syncthreads();

    // --- main loop: compute stage s while prefetching s+1 ---
    for (int c = 0; c < NCH; c++) {
        const int s = c & 1;
        if (c + 1 < NCH) { loadA(c + 1); loadB(c + 1); }

        const uint32_t* Au = (const uint32_t*)(As + s * A_WORDS);
        const uint32_t* Bu = (const uint32_t*)(Bs + s * B_WORDS);

        #pragma unroll
        for (int kk = 0; kk < 4; kk++) {
            const int kb = kk * 8;
            uint32_t afr[4][4], bfr[4][2];
            #pragma unroll
            for (int mi = 0; mi < 4; mi++) {
                int mr = wm * 64 + mi * 16 + g;
                afr[mi][0] = Au[mr * LDA + kb + t4];
                afr[mi][1] = Au[(mr + 8) * LDA + kb + t4];
                afr[mi][2] = Au[mr * LDA + kb + t4 + 4];
                afr[mi][3] = Au[(mr + 8) * LDA + kb + t4 + 4];
            }
            #pragma unroll
            for (int ni = 0; ni < 4; ni++) {
                int nc = wn * 32 + ni * 8 + g;
                bfr[ni][0] = Bu[(kb + t4) * LDB + nc];
                bfr[ni][1] = Bu[(kb + t4 + 4) * LDB + nc];
            }
            #pragma unroll
            for (int mi = 0; mi < 4; mi++)
                #pragma unroll
                for (int ni = 0; ni < 4; ni++)
                    mma_tf32(acc[mi][ni], afr[mi], bfr[ni]);
        }

        if (c + 1 < NCH) {
            stsA((c + 1) & 1); stsB((c + 1) & 1);
            __syncthreads();
        }
    }

    // --- epilogue: bias + relu -> g_feat ---
    // c0,c1: row g,   cols 2*t4, 2*t4+1 ;  c2,c3: row g+8, same cols
    #pragma unroll
    for (int mi = 0; mi < 4; mi++) {
        #pragma unroll
        for (int ni = 0; ni < 4; ni++) {
            int m = m0 + wm * 64 + mi * 16 + g;
            int n = n0 + wn * 32 + ni * 8 + 2 * t4;
            float b0 = bias[n], b1 = bias[n + 1];
            float2 v0, v1;
            v0.x = fmaxf(acc[mi][ni][0] + b0, 0.f);
            v0.y = fmaxf(acc[mi][ni][1] + b1, 0.f);
            v1.x = fmaxf(acc[mi][ni][2] + b0, 0.f);
            v1.y = fmaxf(acc[mi][ni][3] + b1, 0.f);
            *(float2*)&g_feat[(size_t)m * CCH + n]       = v0;
            *(float2*)&g_feat[(size_t)(m + 8) * CCH + n] = v1;
        }
    }
}

// ---------------------------------------------------------------------------
// 2) ROI align (bilinear, 7x7) + mean + notrack mask.
//    One block per roi; one thread per channel (coalesced feature reads).
// ---------------------------------------------------------------------------
__global__ __launch_bounds__(256) void roi_kernel(const float* __restrict__ boxes) {
    const int roi = blockIdx.x;
    const int b = roi >> 4;
    const int c = threadIdx.x;

    float4 box = *(const float4*)&boxes[roi * 4];
    float ymin = box.x, xmin = box.y, ymax = box.z, xmax = box.w;
    bool empty = (ymin == -1.f) && (xmin == -1.f) && (ymax == -1.f) && (xmax == -1.f);
    if (empty) { g_obj[roi * CCH + c] = 0.f; return; }

    int y0[S_ROI], y1[S_ROI], x0[S_ROI], x1[S_ROI];
    float wy[S_ROI], wx[S_ROI];
    #pragma unroll
    for (int i = 0; i < S_ROI; i++) {
        float step = ((float)i + 0.5f) / (float)S_ROI;
        float ys = ymin + (ymax - ymin) * step;
        float xs = xmin + (xmax - xmin) * step;
        float py = ys * (float)FH - 0.5f;
        float px = xs * (float)FW - 0.5f;
        float y0f = floorf(py), x0f = floorf(px);
        wy[i] = py - y0f;  wx[i] = px - x0f;
        int yi = (int)y0f, xi = (int)x0f;
        y0[i] = min(max(yi, 0), FH - 1);
        y1[i] = min(max(yi + 1, 0), FH - 1);
        x0[i] = min(max(xi, 0), FW - 1);
        x1[i] = min(max(xi + 1, 0), FW - 1);
    }

    const float* fb = g_feat + (size_t)b * FH * FW * CCH;
    float acc = 0.f;
    #pragma unroll
    for (int i = 0; i < S_ROI; i++) {
        const float* ry0 = fb + y0[i] * (FW * CCH);
        const float* ry1 = fb + y1[i] * (FW * CCH);
        float wyi = wy[i];
        #pragma unroll
        for (int j = 0; j < S_ROI; j++) {
            float wxj = wx[j];
            float f00 = ry0[x0[j] * CCH + c];
            float f01 = ry0[x1[j] * CCH + c];
            float f10 = ry1[x0[j] * CCH + c];
            float f11 = ry1[x1[j] * CCH + c];
            acc += (1.f - wyi) * (1.f - wxj) * f00
                 + (1.f - wyi) * wxj         * f01
                 + wyi         * (1.f - wxj) * f10
                 + wyi         * wxj         * f11;
        }
    }
    g_obj[roi * CCH + c] = acc * (1.f / (S_ROI * S_ROI));
}

// ---------------------------------------------------------------------------
// 3) Dense: out[256,256] = obj[256,256] @ Wd[256,256] + bd.
//    grid=64 (4 rows/block), k unrolled x8 with register prefetch (MLP=8).
// ---------------------------------------------------------------------------
__global__ __launch_bounds__(256) void dense_kernel(
    const float* __restrict__ Wd, const float* __restrict__ bd,
    float* __restrict__ out)
{
    __shared__ float sObj[4][DDIM];
    const int r0 = blockIdx.x * 4;
    const int tid = threadIdx.x;

    #pragma unroll
    for (int r = 0; r < 4; r++)
        sObj[r][tid] = g_obj[(r0 + r) * CCH + tid];
    __syncthreads();

    float acc[4] = {0.f, 0.f, 0.f, 0.f};
    #pragma unroll 1
    for (int k0 = 0; k0 < CCH; k0 += 8) {
        float w[8];
        #pragma unroll
        for (int u = 0; u < 8; u++) w[u] = Wd[(k0 + u) * DDIM + tid];
        #pragma unroll
        for (int u = 0; u < 8; u++) {
            #pragma unroll
            for (int r = 0; r < 4; r++)
                acc[r] += sObj[r][k0 + u] * w[u];
        }
    }
    float bb = bd[tid];
    #pragma unroll
    for (int r = 0; r < 4; r++)
        out[(r0 + r) * DDIM + tid] = acc[r] + bb;
}

// ---------------------------------------------------------------------------
// Launch
// Inputs: 0 images[16,512,512,3] f32, 1 bboxes[16,16,4] f32,
//         2 conv_w[16,16,3,256] f32, 3 conv_b[256] f32,
//         4 dense_w[256,256] f32, 5 dense_b[256] f32
// Output: [16,16,256] f32
// ---------------------------------------------------------------------------
extern "C" void kernel_launch(void* const* d_in, const int* in_sizes, int n_in,
                              void* d_out, int out_size) {
    const float* images  = (const float*)d_in[0];
    const float* bboxes  = (const float*)d_in[1];
    const float* conv_w  = (const float*)d_in[2];
    const float* conv_b  = (const float*)d_in[3];
    const float* dense_w = (const float*)d_in[4];
    const float* dense_b = (const float*)d_in[5];
    float* out = (float*)d_out;

    static bool attr_set = false;
    if (!attr_set) {
        cudaFuncSetAttribute(conv_mma_kernel,
                             cudaFuncAttributeMaxDynamicSharedMemorySize, SMEM_BYTES);
        attr_set = true;
    }

    dim3 grid(CCH / 128, M_TOT / 128);   // (2, 128)
    conv_mma_kernel<<<grid, 256, SMEM_BYTES>>>(images, conv_w, conv_b);

    roi_kernel<<<BDIM * NBOX, CCH>>>(bboxes);

    dense_kernel<<<(BDIM * NBOX) / 4, DDIM>>>(dense_w, dense_b, out);
}

// round 4
// speedup vs baseline: 2.8271x; 1.0548x over previous
#include <cuda_runtime.h>
#include <cuda_bf16.h>
#include <cstdint>

// ---------------------------------------------------------------------------
// Problem constants
// ---------------------------------------------------------------------------
#define BDIM   16
#define FH     32
#define FW     32
#define NBOX   16
#define CCH    256     // conv out channels
#define DDIM   256     // dense out
#define KDIM   768     // 16*16*3
#define M_TOT  16384   // B*32*32
#define S_ROI  7

// Scratch (static __device__ — no allocations allowed)
__device__ float g_feat[M_TOT * CCH];       // conv+relu feat [16384, 256]
__device__ float g_obj[BDIM * NBOX * CCH];  // pooled rois   [256, 256]

// ---------------------------------------------------------------------------
// tf32 mma.sync helpers (sm_80+ path; compiles for plain sm_100 target)
// ---------------------------------------------------------------------------
__device__ __forceinline__ uint32_t f2tf32(float f) {
    uint32_t r;
    asm("cvt.rna.tf32.f32 %0, %1;" : "=r"(r) : "f"(f));
    return r;
}

__device__ __forceinline__ void mma_tf32(float* d, const uint32_t* a, const uint32_t* b) {
    asm volatile(
        "mma.sync.aligned.m16n8k8.row.col.f32.tf32.tf32.f32 "
        "{%0,%1,%2,%3}, {%4,%5,%6,%7}, {%8,%9}, {%0,%1,%2,%3};"
        : "+f"(d[0]), "+f"(d[1]), "+f"(d[2]), "+f"(d[3])
        : "r"(a[0]), "r"(a[1]), "r"(a[2]), "r"(a[3]), "r"(b[0]), "r"(b[1]));
}

// ---------------------------------------------------------------------------
// 1) Conv-as-GEMM with fused im2col.
//    C[16384,256] = A[16384,768] @ W[768,256], + bias, ReLU.
//    CTA tile 128(M) x 128(N), BK=32, double-buffered SMEM.
//    8 warps, each 64(M) x 32(N) -> mma grid 4x4 of m16n8k8.
// ---------------------------------------------------------------------------
#define BK   32
#define NCH  (KDIM / BK)      // 24 k-chunks
#define LDA  36               // padded (conflict-free A frag LDS: bank = 4m+k)
#define LDB  132              // padded
#define A_WORDS (128 * LDA)   // per stage
#define B_WORDS (BK * LDB)
#define SMEM_BYTES ((2 * A_WORDS + 2 * B_WORDS) * 4)   // 70656

__global__ __launch_bounds__(256, 1) void conv_mma_kernel(
    const float* __restrict__ img,     // [16,512,512,3]
    const float* __restrict__ W,       // [768,256] (HWIO flat) — already [k][n]
    const float* __restrict__ bias)    // [256]
{
    extern __shared__ float smem[];
    float* As = smem;                  // [2][128][LDA]
    float* Bs = smem + 2 * A_WORDS;    // [2][BK][LDB]

    const int tid = threadIdx.x;
    const int wid = tid >> 5;
    const int lid = tid & 31;
    const int g   = lid >> 2;          // group id 0..7
    const int t4  = lid & 3;           // thread-in-group 0..3
    const int wm  = wid & 1;           // 2 warps in M (64 each)
    const int wn  = wid >> 1;          // 4 warps in N (32 each)

    const int n0 = blockIdx.x * 128;   // 0 or 128
    const int m0 = blockIdx.y * 128;

    float acc[4][4][4];
    #pragma unroll
    for (int i = 0; i < 4; i++)
        #pragma unroll
        for (int j = 0; j < 4; j++)
            #pragma unroll
            for (int r = 0; r < 4; r++) acc[i][j][r] = 0.f;

    float4 aReg[4], bReg[4];

    // --- tile loaders: global -> registers (im2col fused for A) ---
    auto loadA = [&](int c) {
        const int k0 = c * BK;
        #pragma unroll
        for (int i = 0; i < 4; i++) {
            int f4  = tid + i * 256;        // 0..1023
            int row = f4 >> 3;              // 0..127
            int c4  = (f4 & 7) * 4;         // 0..28
            int m   = m0 + row;
            int b   = m >> 10;
            int oy  = (m >> 5) & 31;
            int ox  = m & 31;
            int k   = k0 + c4;
            int ky  = k / 48;
            int rem = k - ky * 48;          // within 48-float pixel run; 4|48 so no crossing
            aReg[i] = *(const float4*)(
                img + (size_t)((b * 512 + oy * 16 + ky) * 512 + ox * 16) * 3 + rem);
        }
    };
    auto loadB = [&](int c) {
        const int k0 = c * BK;
        #pragma unroll
        for (int i = 0; i < 4; i++) {
            int f4  = tid + i * 256;        // 0..1023
            int row = f4 >> 5;              // 0..31
            int c4  = (f4 & 31) * 4;        // 0..124
            bReg[i] = *(const float4*)&W[(k0 + row) * CCH + n0 + c4];
        }
    };
    // --- registers -> SMEM with tf32 rounding ---
    auto stsA = [&](int s) {
        float* dst = As + s * A_WORDS;
        #pragma unroll
        for (int i = 0; i < 4; i++) {
            int f4  = tid + i * 256;
            int row = f4 >> 3;
            int c4  = (f4 & 7) * 4;
            uint4 v;
            v.x = f2tf32(aReg[i].x); v.y = f2tf32(aReg[i].y);
            v.z = f2tf32(aReg[i].z); v.w = f2tf32(aReg[i].w);
            *(uint4*)&dst[row * LDA + c4] = v;
        }
    };
    auto stsB = [&](int s) {
        float* dst = Bs + s * B_WORDS;
        #pragma unroll
        for (int i = 0; i < 4; i++) {
            int f4  = tid + i * 256;
            int row = f4 >> 5;
            int c4  = (f4 & 31) * 4;
            uint4 v;
            v.x = f2tf32(bReg[i].x); v.y = f2tf32(bReg[i].y);
            v.z = f2tf32(bReg[i].z); v.w = f2tf32(bReg[i].w);
            *(uint4*)&dst[row * LDB + c4] = v;
        }
    };

    // --- prologue ---
    loadA(0); loadB(0);
    stsA(0);  stsB(0);
    __syncthreads();

    // --- main loop: compute stage s while prefetching s+1 ---
    for (int c = 0; c < NCH; c++) {
        const int s = c & 1;
        if (c + 1 < NCH) { loadA(c + 1); loadB(c + 1); }

        const uint32_t* Au = (const uint32_t*)(As + s * A_WORDS);
        const uint32_t* Bu = (const uint32_t*)(Bs + s * B_WORDS);

        #pragma unroll
        for (int kk = 0; kk < 4; kk++) {
            const int kb = kk * 8;
            uint32_t afr[4][4], bfr[4][2];
            #pragma unroll
            for (int mi = 0; mi < 4; mi++) {
                int mr = wm * 64 + mi * 16 + g;
                afr[mi][0] = Au[mr * LDA + kb + t4];
                afr[mi][1] = Au[(mr + 8) * LDA + kb + t4];
                afr[mi][2] = Au[mr * LDA + kb + t4 + 4];
                afr[mi][3] = Au[(mr + 8) * LDA + kb + t4 + 4];
            }
            #pragma unroll
            for (int ni = 0; ni < 4; ni++) {
                int nc = wn * 32 + ni * 8 + g;
                bfr[ni][0] = Bu[(kb + t4) * LDB + nc];
                bfr[ni][1] = Bu[(kb + t4 + 4) * LDB + nc];
            }
            #pragma unroll
            for (int mi = 0; mi < 4; mi++)
                #pragma unroll
                for (int ni = 0; ni < 4; ni++)
                    mma_tf32(acc[mi][ni], afr[mi], bfr[ni]);
        }

        if (c + 1 < NCH) {
            stsA((c + 1) & 1); stsB((c + 1) & 1);
            __syncthreads();
        }
    }

    // --- epilogue: bias + relu -> g_feat ---
    // c0,c1: row g,   cols 2*t4, 2*t4+1 ;  c2,c3: row g+8, same cols
    #pragma unroll
    for (int mi = 0; mi < 4; mi++) {
        #pragma unroll
        for (int ni = 0; ni < 4; ni++) {
            int m = m0 + wm * 64 + mi * 16 + g;
            int n = n0 + wn * 32 + ni * 8 + 2 * t4;
            float b0 = bias[n], b1 = bias[n + 1];
            float2 v0, v1;
            v0.x = fmaxf(acc[mi][ni][0] + b0, 0.f);
            v0.y = fmaxf(acc[mi][ni][1] + b1, 0.f);
            v1.x = fmaxf(acc[mi][ni][2] + b0, 0.f);
            v1.y = fmaxf(acc[mi][ni][3] + b1, 0.f);
            *(float2*)&g_feat[(size_t)m * CCH + n]       = v0;
            *(float2*)&g_feat[(size_t)(m + 8) * CCH + n] = v1;
        }
    }
}

// ---------------------------------------------------------------------------
// 2) ROI align (bilinear, 7x7) + mean + notrack mask.
//    One block per roi; one thread per channel (coalesced feature reads).
// ---------------------------------------------------------------------------
__global__ __launch_bounds__(256) void roi_kernel(const float* __restrict__ boxes) {
    const int roi = blockIdx.x;
    const int b = roi >> 4;
    const int c = threadIdx.x;

    float4 box = *(const float4*)&boxes[roi * 4];
    float ymin = box.x, xmin = box.y, ymax = box.z, xmax = box.w;
    bool empty = (ymin == -1.f) && (xmin == -1.f) && (ymax == -1.f) && (xmax == -1.f);
    if (empty) { g_obj[roi * CCH + c] = 0.f; return; }

    int y0[S_ROI], y1[S_ROI], x0[S_ROI], x1[S_ROI];
    float wy[S_ROI], wx[S_ROI];
    #pragma unroll
    for (int i = 0; i < S_ROI; i++) {
        float step = ((float)i + 0.5f) / (float)S_ROI;
        float ys = ymin + (ymax - ymin) * step;
        float xs = xmin + (xmax - xmin) * step;
        float py = ys * (float)FH - 0.5f;
        float px = xs * (float)FW - 0.5f;
        float y0f = floorf(py), x0f = floorf(px);
        wy[i] = py - y0f;  wx[i] = px - x0f;
        int yi = (int)y0f, xi = (int)x0f;
        y0[i] = min(max(yi, 0), FH - 1);
        y1[i] = min(max(yi + 1, 0), FH - 1);
        x0[i] = min(max(xi, 0), FW - 1);
        x1[i] = min(max(xi + 1, 0), FW - 1);
    }

    const float* fb = g_feat + (size_t)b * FH * FW * CCH;
    float acc = 0.f;
    #pragma unroll
    for (int i = 0; i < S_ROI; i++) {
        const float* ry0 = fb + y0[i] * (FW * CCH);
        const float* ry1 = fb + y1[i] * (FW * CCH);
        float wyi = wy[i];
        #pragma unroll
        for (int j = 0; j < S_ROI; j++) {
            float wxj = wx[j];
            float f00 = ry0[x0[j] * CCH + c];
            float f01 = ry0[x1[j] * CCH + c];
            float f10 = ry1[x0[j] * CCH + c];
            float f11 = ry1[x1[j] * CCH + c];
            acc += (1.f - wyi) * (1.f - wxj) * f00
                 + (1.f - wyi) * wxj         * f01
                 + wyi         * (1.f - wxj) * f10
                 + wyi         * wxj         * f11;
        }
    }
    g_obj[roi * CCH + c] = acc * (1.f / (S_ROI * S_ROI));
}

// ---------------------------------------------------------------------------
// 3) Dense: out[256,256] = obj[256,256] @ Wd[256,256] + bd.
//    grid=64 (4 rows/block), k unrolled x8 with register prefetch (MLP=8).
// ---------------------------------------------------------------------------
__global__ __launch_bounds__(256) void dense_kernel(
    const float* __restrict__ Wd, const float* __restrict__ bd,
    float* __restrict__ out)
{
    __shared__ float sObj[4][DDIM];
    const int r0 = blockIdx.x * 4;
    const int tid = threadIdx.x;

    #pragma unroll
    for (int r = 0; r < 4; r++)
        sObj[r][tid] = g_obj[(r0 + r) * CCH + tid];
    __syncthreads();

    float acc[4] = {0.f, 0.f, 0.f, 0.f};
    #pragma unroll 1
    for (int k0 = 0; k0 < CCH; k0 += 8) {
        float w[8];
        #pragma unroll
        for (int u = 0; u < 8; u++) w[u] = Wd[(k0 + u) * DDIM + tid];
        #pragma unroll
        for (int u = 0; u < 8; u++) {
            #pragma unroll
            for (int r = 0; r < 4; r++)
                acc[r] += sObj[r][k0 + u] * w[u];
        }
    }
    float bb = bd[tid];
    #pragma unroll
    for (int r = 0; r < 4; r++)
        out[(r0 + r) * DDIM + tid] = acc[r] + bb;
}

// ---------------------------------------------------------------------------
// Launch
// Inputs: 0 images[16,512,512,3] f32, 1 bboxes[16,16,4] f32,
//         2 conv_w[16,16,3,256] f32, 3 conv_b[256] f32,
//         4 dense_w[256,256] f32, 5 dense_b[256] f32
// Output: [16,16,256] f32
// ---------------------------------------------------------------------------
extern "C" void kernel_launch(void* const* d_in, const int* in_sizes, int n_in,
                              void* d_out, int out_size) {
    const float* images  = (const float*)d_in[0];
    const float* bboxes  = (const float*)d_in[1];
    const float* conv_w  = (const float*)d_in[2];
    const float* conv_b  = (const float*)d_in[3];
    const float* dense_w = (const float*)d_in[4];
    const float* dense_b = (const float*)d_in[5];
    float* out = (float*)d_out;

    static bool attr_set = false;
    if (!attr_set) {
        cudaFuncSetAttribute(conv_mma_kernel,
                             cudaFuncAttributeMaxDynamicSharedMemorySize, SMEM_BYTES);
        attr_set = true;
    }

    dim3 grid(CCH / 128, M_TOT / 128);   // (2, 128)
    conv_mma_kernel<<<grid, 256, SMEM_BYTES>>>(images, conv_w, conv_b);

    roi_kernel<<<BDIM * NBOX, CCH>>>(bboxes);

    dense_kernel<<<(BDIM * NBOX) / 4, DDIM>>>(dense_w, dense_b, out);
}

// round 5
// speedup vs baseline: 3.1604x; 1.1179x over previous
#include <cuda_runtime.h>
#include <cuda_bf16.h>
#include <cstdint>

// ---------------------------------------------------------------------------
// Problem constants
// ---------------------------------------------------------------------------
#define BDIM   16
#define FH     32
#define FW     32
#define NBOX   16
#define CCH    256     // conv out channels
#define DDIM   256     // dense out
#define KDIM   768     // 16*16*3
#define M_TOT  16384   // B*32*32
#define S_ROI  7

// Scratch (static __device__ — no allocations allowed)
__device__ float g_feat[M_TOT * CCH];       // conv+relu feat [16384, 256]
__device__ float g_obj[BDIM * NBOX * CCH];  // pooled rois   [256, 256]

// ---------------------------------------------------------------------------
// helpers
// ---------------------------------------------------------------------------
__device__ __forceinline__ uint32_t smem_to_u32(const void* smem_ptr) {
    uint32_t addr;
    asm("{ .reg .u64 tmp; cvta.to.shared.u64 tmp, %1; cvt.u32.u64 %0, tmp; }"
        : "=r"(addr) : "l"(smem_ptr));
    return addr;
}
__device__ __forceinline__ uint32_t f2tf32(float f) {
    uint32_t r;
    asm("cvt.rna.tf32.f32 %0, %1;" : "=r"(r) : "f"(f));
    return r;
}
__device__ __forceinline__ void mma_tf32(float* d, const uint32_t* a, const uint32_t* b) {
    asm volatile(
        "mma.sync.aligned.m16n8k8.row.col.f32.tf32.tf32.f32 "
        "{%0,%1,%2,%3}, {%4,%5,%6,%7}, {%8,%9}, {%0,%1,%2,%3};"
        : "+f"(d[0]), "+f"(d[1]), "+f"(d[2]), "+f"(d[3])
        : "r"(a[0]), "r"(a[1]), "r"(a[2]), "r"(a[3]), "r"(b[0]), "r"(b[1]));
}
__device__ __forceinline__ void cp16(uint32_t smem_dst, const void* gsrc) {
    asm volatile("cp.async.cg.shared.global [%0], [%1], 16;"
                 :: "r"(smem_dst), "l"(gsrc));
}
#define CP_COMMIT()  asm volatile("cp.async.commit_group;" ::: "memory")
#define CP_WAIT2()   asm volatile("cp.async.wait_group 2;"  ::: "memory")

// ---------------------------------------------------------------------------
// 1) Conv-as-GEMM, fused im2col, cp.async 3-stage pipeline.
//    C[16384,256] = A[16384,768] @ W[768,256], + bias, ReLU.
//    CTA tile 128(M) x 128(N), BK=32; 8 warps, each 64(M) x 32(N).
// ---------------------------------------------------------------------------
#define BK     32
#define NCH    (KDIM / BK)          // 24 k-chunks
#define LDA    36                   // pad: conflict-free A frag LDS
#define LDB    136                  // pad: conflict-free B frag LDS
#define A_WORDS (128 * LDA)         // 4608
#define B_WORDS (BK * LDB)          // 4352
#define STG_WORDS (A_WORDS + B_WORDS)
#define STAGES 3
#define SMEM_BYTES (STAGES * STG_WORDS * 4)   // 107520

__global__ __launch_bounds__(256, 2) void conv_mma_kernel(
    const float* __restrict__ img,     // [16,512,512,3]
    const float* __restrict__ W,       // [768,256] (HWIO flat) — already [k][n]
    const float* __restrict__ bias)    // [256]
{
    extern __shared__ float smem[];
    const uint32_t sb = smem_to_u32(smem);

    const int tid = threadIdx.x;
    const int wid = tid >> 5;
    const int lid = tid & 31;
    const int g   = lid >> 2;          // 0..7
    const int t4  = lid & 3;           // 0..3
    const int wm  = wid & 1;           // 2 warps in M
    const int wn  = wid >> 1;          // 4 warps in N

    const int n0 = blockIdx.x * 128;
    const int m0 = blockIdx.y * 128;

    // Per-thread cp.async source bases (i = 0..3 for A, 0..3 for B)
    const float* aBase[4];
    const float* bBase[4];
    #pragma unroll
    for (int i = 0; i < 4; i++) {
        int f4  = tid + i * 256;               // 0..1023
        int row = f4 >> 3;                      // A row 0..127
        int m   = m0 + row;
        int b   = m >> 10;
        int oy  = (m >> 5) & 31;
        int ox  = m & 31;
        aBase[i] = img + (size_t)((b * 512 + oy * 16) * 512 + ox * 16) * 3;
        int brow = f4 >> 5;                     // B row 0..31
        int bc4  = (f4 & 31) * 4;
        bBase[i] = W + (size_t)brow * CCH + n0 + bc4;
    }

    auto issue = [&](int c) {
        const int k0 = c * BK;
        const uint32_t soff = sb + (uint32_t)(c % STAGES) * (STG_WORDS * 4);
        #pragma unroll
        for (int i = 0; i < 4; i++) {
            int f4  = tid + i * 256;
            int row = f4 >> 3;
            int c4  = (f4 & 7) * 4;
            int k   = k0 + c4;
            int ky  = k / 48;
            int rem = k - ky * 48;              // 4 | 48 -> 16B never crosses a pixel run
            cp16(soff + (uint32_t)(row * LDA + c4) * 4,
                 aBase[i] + ky * 1536 + rem);
        }
        #pragma unroll
        for (int i = 0; i < 4; i++) {
            int f4   = tid + i * 256;
            int brow = f4 >> 5;
            cp16(soff + (uint32_t)(A_WORDS + brow * LDB + ((f4 & 31) * 4)) * 4,
                 bBase[i] + (size_t)k0 * CCH);
        }
        CP_COMMIT();
    };

    float acc[4][4][4];
    #pragma unroll
    for (int i = 0; i < 4; i++)
        #pragma unroll
        for (int j = 0; j < 4; j++)
            #pragma unroll
            for (int r = 0; r < 4; r++) acc[i][j][r] = 0.f;

    // --- prologue: fill the 3 stages ---
    issue(0); issue(1); issue(2);

    // --- main loop ---
    for (int c = 0; c < NCH; c++) {
        CP_WAIT2();                 // chunk c landed
        __syncthreads();

        const float* As = smem + (c % STAGES) * STG_WORDS;
        const float* Bs = As + A_WORDS;

        #pragma unroll
        for (int kk = 0; kk < 4; kk++) {
            const int kb = kk * 8;
            uint32_t afr[4][4], bfr[4][2];
            #pragma unroll
            for (int mi = 0; mi < 4; mi++) {
                int mr = wm * 64 + mi * 16 + g;
                afr[mi][0] = f2tf32(As[mr * LDA + kb + t4]);
                afr[mi][1] = f2tf32(As[(mr + 8) * LDA + kb + t4]);
                afr[mi][2] = f2tf32(As[mr * LDA + kb + t4 + 4]);
                afr[mi][3] = f2tf32(As[(mr + 8) * LDA + kb + t4 + 4]);
            }
            #pragma unroll
            for (int ni = 0; ni < 4; ni++) {
                int nc = wn * 32 + ni * 8 + g;
                bfr[ni][0] = f2tf32(Bs[(kb + t4) * LDB + nc]);
                bfr[ni][1] = f2tf32(Bs[(kb + t4 + 4) * LDB + nc]);
            }
            #pragma unroll
            for (int mi = 0; mi < 4; mi++)
                #pragma unroll
                for (int ni = 0; ni < 4; ni++)
                    mma_tf32(acc[mi][ni], afr[mi], bfr[ni]);
        }

        __syncthreads();            // all warps done reading stage c%3
        if (c + STAGES < NCH) issue(c + STAGES);
        else CP_COMMIT();           // keep group count aligned for wait_group
    }

    // --- epilogue: bias + relu -> g_feat ---
    #pragma unroll
    for (int mi = 0; mi < 4; mi++) {
        #pragma unroll
        for (int ni = 0; ni < 4; ni++) {
            int m = m0 + wm * 64 + mi * 16 + g;
            int n = n0 + wn * 32 + ni * 8 + 2 * t4;
            float b0 = bias[n], b1 = bias[n + 1];
            float2 v0, v1;
            v0.x = fmaxf(acc[mi][ni][0] + b0, 0.f);
            v0.y = fmaxf(acc[mi][ni][1] + b1, 0.f);
            v1.x = fmaxf(acc[mi][ni][2] + b0, 0.f);
            v1.y = fmaxf(acc[mi][ni][3] + b1, 0.f);
            *(float2*)&g_feat[(size_t)m * CCH + n]       = v0;
            *(float2*)&g_feat[(size_t)(m + 8) * CCH + n] = v1;
        }
    }
}

// ---------------------------------------------------------------------------
// 2) ROI align (bilinear, 7x7) + mean + notrack mask.
// ---------------------------------------------------------------------------
__global__ __launch_bounds__(256) void roi_kernel(const float* __restrict__ boxes) {
    const int roi = blockIdx.x;
    const int b = roi >> 4;
    const int c = threadIdx.x;

    float4 box = *(const float4*)&boxes[roi * 4];
    float ymin = box.x, xmin = box.y, ymax = box.z, xmax = box.w;
    bool empty = (ymin == -1.f) && (xmin == -1.f) && (ymax == -1.f) && (xmax == -1.f);
    if (empty) { g_obj[roi * CCH + c] = 0.f; return; }

    int y0[S_ROI], y1[S_ROI], x0[S_ROI], x1[S_ROI];
    float wy[S_ROI], wx[S_ROI];
    #pragma unroll
    for (int i = 0; i < S_ROI; i++) {
        float step = ((float)i + 0.5f) / (float)S_ROI;
        float ys = ymin + (ymax - ymin) * step;
        float xs = xmin + (xmax - xmin) * step;
        float py = ys * (float)FH - 0.5f;
        float px = xs * (float)FW - 0.5f;
        float y0f = floorf(py), x0f = floorf(px);
        wy[i] = py - y0f;  wx[i] = px - x0f;
        int yi = (int)y0f, xi = (int)x0f;
        y0[i] = min(max(yi, 0), FH - 1);
        y1[i] = min(max(yi + 1, 0), FH - 1);
        x0[i] = min(max(xi, 0), FW - 1);
        x1[i] = min(max(xi + 1, 0), FW - 1);
    }

    const float* fb = g_feat + (size_t)b * FH * FW * CCH;
    float acc = 0.f;
    #pragma unroll
    for (int i = 0; i < S_ROI; i++) {
        const float* ry0 = fb + y0[i] * (FW * CCH);
        const float* ry1 = fb + y1[i] * (FW * CCH);
        float wyi = wy[i];
        #pragma unroll
        for (int j = 0; j < S_ROI; j++) {
            float wxj = wx[j];
            float f00 = ry0[x0[j] * CCH + c];
            float f01 = ry0[x1[j] * CCH + c];
            float f10 = ry1[x0[j] * CCH + c];
            float f11 = ry1[x1[j] * CCH + c];
            acc += (1.f - wyi) * (1.f - wxj) * f00
                 + (1.f - wyi) * wxj         * f01
                 + wyi         * (1.f - wxj) * f10
                 + wyi         * wxj         * f11;
        }
    }
    g_obj[roi * CCH + c] = acc * (1.f / (S_ROI * S_ROI));
}

// ---------------------------------------------------------------------------
// 3) Dense: out[256,256] = obj[256,256] @ Wd[256,256] + bd.
// ---------------------------------------------------------------------------
__global__ __launch_bounds__(256) void dense_kernel(
    const float* __restrict__ Wd, const float* __restrict__ bd,
    float* __restrict__ out)
{
    __shared__ float sObj[4][DDIM];
    const int r0 = blockIdx.x * 4;
    const int tid = threadIdx.x;

    #pragma unroll
    for (int r = 0; r < 4; r++)
        sObj[r][tid] = g_obj[(r0 + r) * CCH + tid];
    __syncthreads();

    float acc[4] = {0.f, 0.f, 0.f, 0.f};
    #pragma unroll 1
    for (int k0 = 0; k0 < CCH; k0 += 8) {
        float w[8];
        #pragma unroll
        for (int u = 0; u < 8; u++) w[u] = Wd[(k0 + u) * DDIM + tid];
        #pragma unroll
        for (int u = 0; u < 8; u++) {
            #pragma unroll
            for (int r = 0; r < 4; r++)
                acc[r] += sObj[r][k0 + u] * w[u];
        }
    }
    float bb = bd[tid];
    #pragma unroll
    for (int r = 0; r < 4; r++)
        out[(r0 + r) * DDIM + tid] = acc[r] + bb;
}

// ---------------------------------------------------------------------------
// Launch
// ---------------------------------------------------------------------------
extern "C" void kernel_launch(void* const* d_in, const int* in_sizes, int n_in,
                              void* d_out, int out_size) {
    const float* images  = (const float*)d_in[0];
    const float* bboxes  = (const float*)d_in[1];
    const float* conv_w  = (const float*)d_in[2];
    const float* conv_b  = (const float*)d_in[3];
    const float* dense_w = (const float*)d_in[4];
    const float* dense_b = (const float*)d_in[5];
    float* out = (float*)d_out;

    static bool attr_set = false;
    if (!attr_set) {
        cudaFuncSetAttribute(conv_mma_kernel,
                             cudaFuncAttributeMaxDynamicSharedMemorySize, SMEM_BYTES);
        attr_set = true;
    }

    dim3 grid(CCH / 128, M_TOT / 128);   // (2, 128)
    conv_mma_kernel<<<grid, 256, SMEM_BYTES>>>(images, conv_w, conv_b);

    roi_kernel<<<BDIM * NBOX, CCH>>>(bboxes);

    dense_kernel<<<(BDIM * NBOX) / 4, DDIM>>>(dense_w, dense_b, out);
}

// round 6
// speedup vs baseline: 3.5108x; 1.1109x over previous
#include <cuda_runtime.h>
#include <cuda_fp16.h>
#include <cstdint>

// ---------------------------------------------------------------------------
// Problem constants
// ---------------------------------------------------------------------------
#define BDIM   16
#define FH     32
#define FW     32
#define NBOX   16
#define CCH    256     // conv out channels
#define DDIM   256     // dense out
#define KDIM   768     // 16*16*3
#define M_TOT  16384   // B*32*32
#define S_ROI  7

// Scratch (static __device__ — no allocations allowed)
__device__ __half g_Wh[CCH * KDIM];          // W transposed+f16: [256 n][768 k]
__device__ __half g_feat[M_TOT * CCH];       // conv+relu feat [16384, 256] f16
__device__ float  g_obj[BDIM * NBOX * CCH];  // pooled rois   [256, 256]

// ---------------------------------------------------------------------------
// helpers
// ---------------------------------------------------------------------------
__device__ __forceinline__ uint32_t smem_to_u32(const void* smem_ptr) {
    uint32_t addr;
    asm("{ .reg .u64 tmp; cvta.to.shared.u64 tmp, %1; cvt.u32.u64 %0, tmp; }"
        : "=r"(addr) : "l"(smem_ptr));
    return addr;
}
__device__ __forceinline__ uint32_t f2h2(float lo, float hi) {
    uint32_t r;
    asm("cvt.rn.f16x2.f32 %0, %1, %2;" : "=r"(r) : "f"(hi), "f"(lo));
    return r;
}
__device__ __forceinline__ void mma_f16(float* d, const uint32_t* a, const uint32_t* b) {
    asm volatile(
        "mma.sync.aligned.m16n8k16.row.col.f32.f16.f16.f32 "
        "{%0,%1,%2,%3}, {%4,%5,%6,%7}, {%8,%9}, {%0,%1,%2,%3};"
        : "+f"(d[0]), "+f"(d[1]), "+f"(d[2]), "+f"(d[3])
        : "r"(a[0]), "r"(a[1]), "r"(a[2]), "r"(a[3]), "r"(b[0]), "r"(b[1]));
}
__device__ __forceinline__ void cp16(uint32_t smem_dst, const void* gsrc) {
    asm volatile("cp.async.cg.shared.global [%0], [%1], 16;"
                 :: "r"(smem_dst), "l"(gsrc));
}
#define CP_COMMIT() asm volatile("cp.async.commit_group;" ::: "memory")
#define CP_WAIT1()  asm volatile("cp.async.wait_group 1;"  ::: "memory")
#define CP_WAIT0()  asm volatile("cp.async.wait_group 0;"  ::: "memory")

// ---------------------------------------------------------------------------
// 0) W prepass: W[768,256] f32 -> g_Wh[256 n][768 k] f16 (transpose+convert)
// ---------------------------------------------------------------------------
__global__ __launch_bounds__(256) void wprep_kernel(const float* __restrict__ W) {
    __shared__ float t[32][33];
    int kb = blockIdx.x * 32, nb = blockIdx.y * 32;
    int tx = threadIdx.x & 31, ty = threadIdx.x >> 5;   // 32 x 8
    #pragma unroll
    for (int i = 0; i < 32; i += 8)
        t[ty + i][tx] = W[(kb + ty + i) * CCH + nb + tx];
    __syncthreads();
    #pragma unroll
    for (int i = 0; i < 32; i += 8)
        g_Wh[(nb + ty + i) * KDIM + kb + tx] = __float2half_rn(t[tx][ty + i]);
}

// ---------------------------------------------------------------------------
// 1) Conv-as-GEMM, fused im2col, fp16 m16n8k16 mma, 3-stage cp.async,
//    single barrier per chunk. CTA tile 128x128, 8 warps each 64x32.
// ---------------------------------------------------------------------------
#define BK      32
#define NCH     (KDIM / BK)          // 24
#define LDA     40                   // floats per A row (32 data + 8 pad)
#define LDBT    40                   // halves per B row (32 data + 8 pad)
#define A_BYTES (128 * LDA * 4)      // 20480
#define B_BYTES (128 * LDBT * 2)     // 10240
#define STG_BYTES (A_BYTES + B_BYTES)// 30720
#define STAGES  3
#define SMEM_BYTES (STAGES * STG_BYTES)   // 92160

__global__ __launch_bounds__(256, 2) void conv_mma_kernel(
    const float* __restrict__ img,     // [16,512,512,3]
    const float* __restrict__ bias)    // [256]
{
    extern __shared__ float smem[];
    const uint32_t sb = smem_to_u32(smem);

    const int tid = threadIdx.x;
    const int wid = tid >> 5;
    const int lid = tid & 31;
    const int g   = lid >> 2;          // 0..7
    const int t4  = lid & 3;           // 0..3
    const int wm  = wid & 1;           // 2 warps in M
    const int wn  = wid >> 1;          // 4 warps in N

    const int n0 = blockIdx.x * 128;
    const int m0 = blockIdx.y * 128;

    // cp.async source bases
    const float* aBase[4];
    #pragma unroll
    for (int i = 0; i < 4; i++) {
        int f4  = tid + i * 256;               // 0..1023
        int row = f4 >> 3;                     // 0..127
        int m   = m0 + row;
        int b   = m >> 10;
        int oy  = (m >> 5) & 31;
        int ox  = m & 31;
        aBase[i] = img + (size_t)((b * 512 + oy * 16) * 512 + ox * 16) * 3;
    }
    const __half* bBase[2];
    #pragma unroll
    for (int i = 0; i < 2; i++) {
        int f4  = tid + i * 256;               // 0..511
        int row = f4 >> 2;                     // 0..127
        int q   = f4 & 3;
        bBase[i] = g_Wh + (size_t)(n0 + row) * KDIM + q * 8;
    }

    auto issue = [&](int c) {
        const int k0 = c * BK;
        const uint32_t soff = sb + (uint32_t)(c % STAGES) * STG_BYTES;
        #pragma unroll
        for (int i = 0; i < 4; i++) {
            int f4  = tid + i * 256;
            int row = f4 >> 3;
            int q   = f4 & 7;
            int k   = k0 + q * 4;
            int ky  = k / 48;
            int rem = k - ky * 48;             // 4 | 48 -> never crosses pixel run
            cp16(soff + (uint32_t)(row * (LDA * 4) + q * 16),
                 aBase[i] + ky * 1536 + rem);
        }
        #pragma unroll
        for (int i = 0; i < 2; i++) {
            int f4  = tid + i * 256;
            int row = f4 >> 2;
            int q   = f4 & 3;
            cp16(soff + (uint32_t)(A_BYTES + row * (LDBT * 2) + q * 16),
                 bBase[i] + k0);
        }
        CP_COMMIT();
    };

    float acc[4][4][4];
    #pragma unroll
    for (int i = 0; i < 4; i++)
        #pragma unroll
        for (int j = 0; j < 4; j++)
            #pragma unroll
            for (int r = 0; r < 4; r++) acc[i][j][r] = 0.f;

    // prologue: 2 chunks in flight
    issue(0); issue(1);

    for (int c = 0; c < NCH; c++) {
        if (c + 1 < NCH) CP_WAIT1(); else CP_WAIT0();
        __syncthreads();                       // frees stage (c+2)%3, chunk c visible
        if (c + 2 < NCH) issue(c + 2);

        const float*    As  = smem + (c % STAGES) * (STG_BYTES / 4);
        const uint32_t* Bsu = (const uint32_t*)((const char*)As + A_BYTES);

        #pragma unroll
        for (int kk = 0; kk < 2; kk++) {       // two k16 steps per chunk
            const int ka = kk * 16 + 2 * t4;   // A k offset (floats)
            uint32_t afr[4][4], bfr[4][2];
            #pragma unroll
            for (int mi = 0; mi < 4; mi++) {
                int mr = wm * 64 + mi * 16 + g;
                float2 v0 = *(const float2*)&As[mr * LDA + ka];
                float2 v1 = *(const float2*)&As[(mr + 8) * LDA + ka];
                float2 v2 = *(const float2*)&As[mr * LDA + ka + 8];
                float2 v3 = *(const float2*)&As[(mr + 8) * LDA + ka + 8];
                afr[mi][0] = f2h2(v0.x, v0.y);
                afr[mi][1] = f2h2(v1.x, v1.y);
                afr[mi][2] = f2h2(v2.x, v2.y);
                afr[mi][3] = f2h2(v3.x, v3.y);
            }
            #pragma unroll
            for (int ni = 0; ni < 4; ni++) {
                int nc = wn * 32 + ni * 8 + g;
                bfr[ni][0] = Bsu[nc * (LDBT / 2) + kk * 8 + t4];
                bfr[ni][1] = Bsu[nc * (LDBT / 2) + kk * 8 + t4 + 4];
            }
            #pragma unroll
            for (int mi = 0; mi < 4; mi++)
                #pragma unroll
                for (int ni = 0; ni < 4; ni++)
                    mma_f16(acc[mi][ni], afr[mi], bfr[ni]);
        }
    }

    // epilogue: bias + relu -> g_feat (f16)
    #pragma unroll
    for (int mi = 0; mi < 4; mi++) {
        #pragma unroll
        for (int ni = 0; ni < 4; ni++) {
            int m = m0 + wm * 64 + mi * 16 + g;
            int n = n0 + wn * 32 + ni * 8 + 2 * t4;
            float b0 = bias[n], b1 = bias[n + 1];
            __half2 h0 = __floats2half2_rn(fmaxf(acc[mi][ni][0] + b0, 0.f),
                                           fmaxf(acc[mi][ni][1] + b1, 0.f));
            __half2 h1 = __floats2half2_rn(fmaxf(acc[mi][ni][2] + b0, 0.f),
                                           fmaxf(acc[mi][ni][3] + b1, 0.f));
            *(__half2*)&g_feat[(size_t)m * CCH + n]       = h0;
            *(__half2*)&g_feat[(size_t)(m + 8) * CCH + n] = h1;
        }
    }
}

// ---------------------------------------------------------------------------
// 2) ROI align (bilinear, 7x7) + mean + notrack mask. feat is f16.
// ---------------------------------------------------------------------------
__global__ __launch_bounds__(256) void roi_kernel(const float* __restrict__ boxes) {
    const int roi = blockIdx.x;
    const int b = roi >> 4;
    const int c = threadIdx.x;

    float4 box = *(const float4*)&boxes[roi * 4];
    float ymin = box.x, xmin = box.y, ymax = box.z, xmax = box.w;
    bool empty = (ymin == -1.f) && (xmin == -1.f) && (ymax == -1.f) && (xmax == -1.f);
    if (empty) { g_obj[roi * CCH + c] = 0.f; return; }

    int y0[S_ROI], y1[S_ROI], x0[S_ROI], x1[S_ROI];
    float wy[S_ROI], wx[S_ROI];
    #pragma unroll
    for (int i = 0; i < S_ROI; i++) {
        float step = ((float)i + 0.5f) / (float)S_ROI;
        float ys = ymin + (ymax - ymin) * step;
        float xs = xmin + (xmax - xmin) * step;
        float py = ys * (float)FH - 0.5f;
        float px = xs * (float)FW - 0.5f;
        float y0f = floorf(py), x0f = floorf(px);
        wy[i] = py - y0f;  wx[i] = px - x0f;
        int yi = (int)y0f, xi = (int)x0f;
        y0[i] = min(max(yi, 0), FH - 1);
        y1[i] = min(max(yi + 1, 0), FH - 1);
        x0[i] = min(max(xi, 0), FW - 1);
        x1[i] = min(max(xi + 1, 0), FW - 1);
    }

    const __half* fb = g_feat + (size_t)b * FH * FW * CCH;
    float acc = 0.f;
    #pragma unroll
    for (int i = 0; i < S_ROI; i++) {
        const __half* ry0 = fb + y0[i] * (FW * CCH);
        const __half* ry1 = fb + y1[i] * (FW * CCH);
        float wyi = wy[i];
        #pragma unroll
        for (int j = 0; j < S_ROI; j++) {
            float wxj = wx[j];
            float f00 = __half2float(ry0[x0[j] * CCH + c]);
            float f01 = __half2float(ry0[x1[j] * CCH + c]);
            float f10 = __half2float(ry1[x0[j] * CCH + c]);
            float f11 = __half2float(ry1[x1[j] * CCH + c]);
            acc += (1.f - wyi) * (1.f - wxj) * f00
                 + (1.f - wyi) * wxj         * f01
                 + wyi         * (1.f - wxj) * f10
                 + wyi         * wxj         * f11;
        }
    }
    g_obj[roi * CCH + c] = acc * (1.f / (S_ROI * S_ROI));
}

// ---------------------------------------------------------------------------
// 3) Dense: out[256,256] = obj[256,256] @ Wd[256,256] + bd.
// ---------------------------------------------------------------------------
__global__ __launch_bounds__(256) void dense_kernel(
    const float* __restrict__ Wd, const float* __restrict__ bd,
    float* __restrict__ out)
{
    __shared__ float sObj[4][DDIM];
    const int r0 = blockIdx.x * 4;
    const int tid = threadIdx.x;

    #pragma unroll
    for (int r = 0; r < 4; r++)
        sObj[r][tid] = g_obj[(r0 + r) * CCH + tid];
    __syncthreads();

    float acc[4] = {0.f, 0.f, 0.f, 0.f};
    #pragma unroll 1
    for (int k0 = 0; k0 < CCH; k0 += 8) {
        float w[8];
        #pragma unroll
        for (int u = 0; u < 8; u++) w[u] = Wd[(k0 + u) * DDIM + tid];
        #pragma unroll
        for (int u = 0; u < 8; u++) {
            #pragma unroll
            for (int r = 0; r < 4; r++)
                acc[r] += sObj[r][k0 + u] * w[u];
        }
    }
    float bb = bd[tid];
    #pragma unroll
    for (int r = 0; r < 4; r++)
        out[(r0 + r) * DDIM + tid] = acc[r] + bb;
}

// ---------------------------------------------------------------------------
// Launch
// ---------------------------------------------------------------------------
extern "C" void kernel_launch(void* const* d_in, const int* in_sizes, int n_in,
                              void* d_out, int out_size) {
    const float* images  = (const float*)d_in[0];
    const float* bboxes  = (const float*)d_in[1];
    const float* conv_w  = (const float*)d_in[2];
    const float* conv_b  = (const float*)d_in[3];
    const float* dense_w = (const float*)d_in[4];
    const float* dense_b = (const float*)d_in[5];
    float* out = (float*)d_out;

    static bool attr_set = false;
    if (!attr_set) {
        cudaFuncSetAttribute(conv_mma_kernel,
                             cudaFuncAttributeMaxDynamicSharedMemorySize, SMEM_BYTES);
        attr_set = true;
    }

    dim3 wgrid(KDIM / 32, CCH / 32);     // (24, 8)
    wprep_kernel<<<wgrid, 256>>>(conv_w);

    dim3 grid(CCH / 128, M_TOT / 128);   // (2, 128)
    conv_mma_kernel<<<grid, 256, SMEM_BYTES>>>(images, conv_b);

    roi_kernel<<<BDIM * NBOX, CCH>>>(bboxes);

    dense_kernel<<<(BDIM * NBOX) / 4, DDIM>>>(dense_w, dense_b, out);
}

// round 7
// speedup vs baseline: 3.8393x; 1.0936x over previous
#include <cuda_runtime.h>
#include <cuda_fp16.h>
#include <cstdint>

// ---------------------------------------------------------------------------
// Problem constants
// ---------------------------------------------------------------------------
#define BDIM   16
#define FH     32
#define FW     32
#define NBOX   16
#define CCH    256     // conv out channels
#define DDIM   256     // dense out
#define KDIM   768     // 16*16*3
#define M_TOT  16384   // B*32*32
#define S_ROI  7

// Scratch (static __device__ — no allocations allowed)
__device__ __half g_Wh[CCH * KDIM];          // W transposed+f16: [256 n][768 k]
__device__ __half g_feat[M_TOT * CCH];       // conv+relu feat [16384, 256] f16
__device__ float  g_obj[BDIM * NBOX * CCH];  // pooled rois   [256, 256]

// ---------------------------------------------------------------------------
// helpers
// ---------------------------------------------------------------------------
__device__ __forceinline__ uint32_t smem_to_u32(const void* smem_ptr) {
    uint32_t addr;
    asm("{ .reg .u64 tmp; cvta.to.shared.u64 tmp, %1; cvt.u32.u64 %0, tmp; }"
        : "=r"(addr) : "l"(smem_ptr));
    return addr;
}
__device__ __forceinline__ uint32_t f2h2(float lo, float hi) {
    uint32_t r;
    asm("cvt.rn.f16x2.f32 %0, %1, %2;" : "=r"(r) : "f"(hi), "f"(lo));
    return r;
}
__device__ __forceinline__ void mma_f16(float* d, const uint32_t* a, const uint32_t* b) {
    asm volatile(
        "mma.sync.aligned.m16n8k16.row.col.f32.f16.f16.f32 "
        "{%0,%1,%2,%3}, {%4,%5,%6,%7}, {%8,%9}, {%0,%1,%2,%3};"
        : "+f"(d[0]), "+f"(d[1]), "+f"(d[2]), "+f"(d[3])
        : "r"(a[0]), "r"(a[1]), "r"(a[2]), "r"(a[3]), "r"(b[0]), "r"(b[1]));
}
__device__ __forceinline__ void cp16(uint32_t smem_dst, const void* gsrc) {
    asm volatile("cp.async.cg.shared.global [%0], [%1], 16;"
                 :: "r"(smem_dst), "l"(gsrc));
}
#define CP_COMMIT() asm volatile("cp.async.commit_group;" ::: "memory")
#define CP_WAIT1()  asm volatile("cp.async.wait_group 1;"  ::: "memory")
#define CP_WAIT0()  asm volatile("cp.async.wait_group 0;"  ::: "memory")

// ---------------------------------------------------------------------------
// 0) W prepass: W[768,256] f32 -> g_Wh[256 n][768 k] f16 (transpose+convert)
// ---------------------------------------------------------------------------
__global__ __launch_bounds__(256) void wprep_kernel(const float* __restrict__ W) {
    __shared__ float t[32][33];
    int kb = blockIdx.x * 32, nb = blockIdx.y * 32;
    int tx = threadIdx.x & 31, ty = threadIdx.x >> 5;   // 32 x 8
    #pragma unroll
    for (int i = 0; i < 32; i += 8)
        t[ty + i][tx] = W[(kb + ty + i) * CCH + nb + tx];
    __syncthreads();
    #pragma unroll
    for (int i = 0; i < 32; i += 8)
        g_Wh[(nb + ty + i) * KDIM + kb + tx] = __float2half_rn(t[tx][ty + i]);
}

// ---------------------------------------------------------------------------
// 1) Conv-as-GEMM, fused im2col, fp16 m16n8k16 mma, 3-stage cp.async,
//    single barrier per chunk. CTA tile 128x128, 8 warps each 64x32.
// ---------------------------------------------------------------------------
#define BK      32
#define NCH     (KDIM / BK)          // 24
#define LDA     40                   // floats per A row (32 data + 8 pad)
#define LDBT    40                   // halves per B row (32 data + 8 pad)
#define A_BYTES (128 * LDA * 4)      // 20480
#define B_BYTES (128 * LDBT * 2)     // 10240
#define STG_BYTES (A_BYTES + B_BYTES)// 30720
#define STAGES  3
#define SMEM_BYTES (STAGES * STG_BYTES)   // 92160

__global__ __launch_bounds__(256, 2) void conv_mma_kernel(
    const float* __restrict__ img,     // [16,512,512,3]
    const float* __restrict__ bias)    // [256]
{
    extern __shared__ float smem[];
    const uint32_t sb = smem_to_u32(smem);

    const int tid = threadIdx.x;
    const int wid = tid >> 5;
    const int lid = tid & 31;
    const int g   = lid >> 2;          // 0..7
    const int t4  = lid & 3;           // 0..3
    const int wm  = wid & 1;           // 2 warps in M
    const int wn  = wid >> 1;          // 4 warps in N

    const int n0 = blockIdx.x * 128;
    const int m0 = blockIdx.y * 128;

    // cp.async source bases
    const float* aBase[4];
    #pragma unroll
    for (int i = 0; i < 4; i++) {
        int f4  = tid + i * 256;               // 0..1023
        int row = f4 >> 3;                     // 0..127
        int m   = m0 + row;
        int b   = m >> 10;
        int oy  = (m >> 5) & 31;
        int ox  = m & 31;
        aBase[i] = img + (size_t)((b * 512 + oy * 16) * 512 + ox * 16) * 3;
    }
    const __half* bBase[2];
    #pragma unroll
    for (int i = 0; i < 2; i++) {
        int f4  = tid + i * 256;               // 0..511
        int row = f4 >> 2;                     // 0..127
        int q   = f4 & 3;
        bBase[i] = g_Wh + (size_t)(n0 + row) * KDIM + q * 8;
    }

    auto issue = [&](int c) {
        const int k0 = c * BK;
        const uint32_t soff = sb + (uint32_t)(c % STAGES) * STG_BYTES;
        #pragma unroll
        for (int i = 0; i < 4; i++) {
            int f4  = tid + i * 256;
            int row = f4 >> 3;
            int q   = f4 & 7;
            int k   = k0 + q * 4;
            int ky  = k / 48;
            int rem = k - ky * 48;             // 4 | 48 -> never crosses pixel run
            cp16(soff + (uint32_t)(row * (LDA * 4) + q * 16),
                 aBase[i] + ky * 1536 + rem);
        }
        #pragma unroll
        for (int i = 0; i < 2; i++) {
            int f4  = tid + i * 256;
            int row = f4 >> 2;
            int q   = f4 & 3;
            cp16(soff + (uint32_t)(A_BYTES + row * (LDBT * 2) + q * 16),
                 bBase[i] + k0);
        }
        CP_COMMIT();
    };

    float acc[4][4][4];
    #pragma unroll
    for (int i = 0; i < 4; i++)
        #pragma unroll
        for (int j = 0; j < 4; j++)
            #pragma unroll
            for (int r = 0; r < 4; r++) acc[i][j][r] = 0.f;

    // prologue: 2 chunks in flight
    issue(0); issue(1);

    for (int c = 0; c < NCH; c++) {
        if (c + 1 < NCH) CP_WAIT1(); else CP_WAIT0();
        __syncthreads();                       // frees stage (c+2)%3, chunk c visible
        if (c + 2 < NCH) issue(c + 2);

        const float*    As  = smem + (c % STAGES) * (STG_BYTES / 4);
        const uint32_t* Bsu = (const uint32_t*)((const char*)As + A_BYTES);

        #pragma unroll
        for (int kk = 0; kk < 2; kk++) {       // two k16 steps per chunk
            const int ka = kk * 16 + 2 * t4;   // A k offset (floats)
            uint32_t afr[4][4], bfr[4][2];
            #pragma unroll
            for (int mi = 0; mi < 4; mi++) {
                int mr = wm * 64 + mi * 16 + g;
                float2 v0 = *(const float2*)&As[mr * LDA + ka];
                float2 v1 = *(const float2*)&As[(mr + 8) * LDA + ka];
                float2 v2 = *(const float2*)&As[mr * LDA + ka + 8];
                float2 v3 = *(const float2*)&As[(mr + 8) * LDA + ka + 8];
                afr[mi][0] = f2h2(v0.x, v0.y);
                afr[mi][1] = f2h2(v1.x, v1.y);
                afr[mi][2] = f2h2(v2.x, v2.y);
                afr[mi][3] = f2h2(v3.x, v3.y);
            }
            #pragma unroll
            for (int ni = 0; ni < 4; ni++) {
                int nc = wn * 32 + ni * 8 + g;
                bfr[ni][0] = Bsu[nc * (LDBT / 2) + kk * 8 + t4];
                bfr[ni][1] = Bsu[nc * (LDBT / 2) + kk * 8 + t4 + 4];
            }
            #pragma unroll
            for (int mi = 0; mi < 4; mi++)
                #pragma unroll
                for (int ni = 0; ni < 4; ni++)
                    mma_f16(acc[mi][ni], afr[mi], bfr[ni]);
        }
    }

    // epilogue: bias + relu -> g_feat (f16)
    #pragma unroll
    for (int mi = 0; mi < 4; mi++) {
        #pragma unroll
        for (int ni = 0; ni < 4; ni++) {
            int m = m0 + wm * 64 + mi * 16 + g;
            int n = n0 + wn * 32 + ni * 8 + 2 * t4;
            float b0 = bias[n], b1 = bias[n + 1];
            __half2 h0 = __floats2half2_rn(fmaxf(acc[mi][ni][0] + b0, 0.f),
                                           fmaxf(acc[mi][ni][1] + b1, 0.f));
            __half2 h1 = __floats2half2_rn(fmaxf(acc[mi][ni][2] + b0, 0.f),
                                           fmaxf(acc[mi][ni][3] + b1, 0.f));
            *(__half2*)&g_feat[(size_t)m * CCH + n]       = h0;
            *(__half2*)&g_feat[(size_t)(m + 8) * CCH + n] = h1;
        }
    }
}

// ---------------------------------------------------------------------------
// 2) ROI align (bilinear, 7x7) + mean + notrack mask. feat is f16.
// ---------------------------------------------------------------------------
__global__ __launch_bounds__(256) void roi_kernel(const float* __restrict__ boxes) {
    const int roi = blockIdx.x;
    const int b = roi >> 4;
    const int c = threadIdx.x;

    float4 box = *(const float4*)&boxes[roi * 4];
    float ymin = box.x, xmin = box.y, ymax = box.z, xmax = box.w;
    bool empty = (ymin == -1.f) && (xmin == -1.f) && (ymax == -1.f) && (xmax == -1.f);
    if (empty) { g_obj[roi * CCH + c] = 0.f; return; }

    int y0[S_ROI], y1[S_ROI], x0[S_ROI], x1[S_ROI];
    float wy[S_ROI], wx[S_ROI];
    #pragma unroll
    for (int i = 0; i < S_ROI; i++) {
        float step = ((float)i + 0.5f) / (float)S_ROI;
        float ys = ymin + (ymax - ymin) * step;
        float xs = xmin + (xmax - xmin) * step;
        float py = ys * (float)FH - 0.5f;
        float px = xs * (float)FW - 0.5f;
        float y0f = floorf(py), x0f = floorf(px);
        wy[i] = py - y0f;  wx[i] = px - x0f;
        int yi = (int)y0f, xi = (int)x0f;
        y0[i] = min(max(yi, 0), FH - 1);
        y1[i] = min(max(yi + 1, 0), FH - 1);
        x0[i] = min(max(xi, 0), FW - 1);
        x1[i] = min(max(xi + 1, 0), FW - 1);
    }

    const __half* fb = g_feat + (size_t)b * FH * FW * CCH;
    float acc = 0.f;
    #pragma unroll
    for (int i = 0; i < S_ROI; i++) {
        const __half* ry0 = fb + y0[i] * (FW * CCH);
        const __half* ry1 = fb + y1[i] * (FW * CCH);
        float wyi = wy[i];
        #pragma unroll
        for (int j = 0; j < S_ROI; j++) {
            float wxj = wx[j];
            float f00 = __half2float(ry0[x0[j] * CCH + c]);
            float f01 = __half2float(ry0[x1[j] * CCH + c]);
            float f10 = __half2float(ry1[x0[j] * CCH + c]);
            float f11 = __half2float(ry1[x1[j] * CCH + c]);
            acc += (1.f - wyi) * (1.f - wxj) * f00
                 + (1.f - wyi) * wxj         * f01
                 + wyi         * (1.f - wxj) * f10
                 + wyi         * wxj         * f11;
        }
    }
    g_obj[roi * CCH + c] = acc * (1.f / (S_ROI * S_ROI));
}

// ---------------------------------------------------------------------------
// 3) Dense: out[256,256] = obj[256,256] @ Wd[256,256] + bd.
//    128 blocks (2 rows each), k unrolled x16 with register prefetch.
//    Latency: 16 exposures of ~L2 latency, overlapped across ~2 blocks/SM.
// ---------------------------------------------------------------------------
__global__ __launch_bounds__(256) void dense_kernel(
    const float* __restrict__ Wd, const float* __restrict__ bd,
    float* __restrict__ out)
{
    __shared__ float sObj[2][DDIM];
    const int r0 = blockIdx.x * 2;
    const int tid = threadIdx.x;

    sObj[0][tid] = g_obj[(size_t)r0 * CCH + tid];
    sObj[1][tid] = g_obj[(size_t)(r0 + 1) * CCH + tid];
    __syncthreads();

    float acc0 = 0.f, acc1 = 0.f;
    #pragma unroll 1
    for (int k0 = 0; k0 < CCH; k0 += 16) {
        float w[16];
        #pragma unroll
        for (int u = 0; u < 16; u++) w[u] = Wd[(k0 + u) * DDIM + tid];
        #pragma unroll
        for (int u = 0; u < 16; u++) {
            acc0 += sObj[0][k0 + u] * w[u];
            acc1 += sObj[1][k0 + u] * w[u];
        }
    }
    float bb = bd[tid];
    out[(size_t)r0 * DDIM + tid]       = acc0 + bb;
    out[(size_t)(r0 + 1) * DDIM + tid] = acc1 + bb;
}

// ---------------------------------------------------------------------------
// Launch
// ---------------------------------------------------------------------------
extern "C" void kernel_launch(void* const* d_in, const int* in_sizes, int n_in,
                              void* d_out, int out_size) {
    const float* images  = (const float*)d_in[0];
    const float* bboxes  = (const float*)d_in[1];
    const float* conv_w  = (const float*)d_in[2];
    const float* conv_b  = (const float*)d_in[3];
    const float* dense_w = (const float*)d_in[4];
    const float* dense_b = (const float*)d_in[5];
    float* out = (float*)d_out;

    static bool attr_set = false;
    if (!attr_set) {
        cudaFuncSetAttribute(conv_mma_kernel,
                             cudaFuncAttributeMaxDynamicSharedMemorySize, SMEM_BYTES);
        attr_set = true;
    }

    dim3 wgrid(KDIM / 32, CCH / 32);     // (24, 8)
    wprep_kernel<<<wgrid, 256>>>(conv_w);

    dim3 grid(CCH / 128, M_TOT / 128);   // (2, 128)
    conv_mma_kernel<<<grid, 256, SMEM_BYTES>>>(images, conv_b);

    roi_kernel<<<BDIM * NBOX, CCH>>>(bboxes);

    dense_kernel<<<(BDIM * NBOX) / 2, DDIM>>>(dense_w, dense_b, out);
}